// round 7
// baseline (speedup 1.0000x reference)
#include <cuda_runtime.h>
#include <cuda_bf16.h>
#include <stdint.h>

#define BB 4096
#define DD 1024
#define RR 256
#define NCTA 128
#define NTHR 512

#define K_W1 1.3512071919596578
#define K_W0 (-1.7024143839193153)
#define K_C1f ((float)(K_W1 * 0.5))
#define K_C2f ((float)((K_W0 + K_W1) * 0.5))
#define K_DT 0.01f

// -------- device-global scratch (no runtime allocation) --------
__device__ __align__(1024) unsigned char g_Ub[16 * 32768];   // U bf16: 16 k-chunks [256n x 64k] SW128
__device__ __align__(1024) unsigned char g_Wb[64 * 8192];    // W bf16: 16 n-chunks x 4 k-tiles [64n x 64k] SW128
__device__ __align__(1024) float g_vf[(size_t)BB * DD];      // v fp32 master

// -------- helpers --------
__device__ __forceinline__ uint32_t swz(uint32_t o) { return o ^ ((o >> 3) & 0x70); }
__device__ __forceinline__ uint32_t s2u(const void* p) {
    uint32_t a; asm("{ .reg .u64 t; cvta.to.shared.u64 t, %1; cvt.u32.u64 %0, t; }" : "=r"(a) : "l"(p)); return a;
}
__device__ __forceinline__ uint32_t bf2u(__nv_bfloat162 b) { return *reinterpret_cast<uint32_t*>(&b); }
__device__ __forceinline__ void mb_init(uint32_t a, uint32_t c) {
    asm volatile("mbarrier.init.shared.b64 [%0], %1;" :: "r"(a), "r"(c) : "memory");
}
__device__ __forceinline__ void mb_expect(uint32_t a, uint32_t b) {
    asm volatile("mbarrier.arrive.expect_tx.shared.b64 _, [%0], %1;" :: "r"(a), "r"(b) : "memory");
}
__device__ __forceinline__ void mb_arrive(uint32_t a) {
    asm volatile("mbarrier.arrive.shared.b64 _, [%0];" :: "r"(a) : "memory");
}
__device__ __forceinline__ void mb_wait(uint32_t a, uint32_t p) {
    asm volatile("{\n\t.reg .pred P;\n\tLW%=:\n\t"
        "mbarrier.try_wait.parity.acquire.cta.shared::cta.b64 P, [%0], %1, 0x989680;\n\t"
        "@P bra LD%=;\n\tbra LW%=;\n\tLD%=:\n\t}" :: "r"(a), "r"(p) : "memory");
}
__device__ __forceinline__ void bulkcp(uint32_t d, const void* s, uint32_t n, uint32_t mb) {
    asm volatile("cp.async.bulk.shared::cluster.global.mbarrier::complete_tx::bytes [%0], [%1], %2, [%3];"
                 :: "r"(d), "l"(s), "r"(n), "r"(mb) : "memory");
}
__device__ __forceinline__ void fence_async_sh() { asm volatile("fence.proxy.async.shared::cta;" ::: "memory"); }
__device__ __forceinline__ void ldsm4(uint32_t* r, uint32_t a) {
    asm volatile("ldmatrix.sync.aligned.m8n8.x4.shared.b16 {%0,%1,%2,%3}, [%4];"
                 : "=r"(r[0]), "=r"(r[1]), "=r"(r[2]), "=r"(r[3]) : "r"(a));
}
__device__ __forceinline__ void ldsm2(uint32_t* r, uint32_t a) {
    asm volatile("ldmatrix.sync.aligned.m8n8.x2.shared.b16 {%0,%1}, [%2];"
                 : "=r"(r[0]), "=r"(r[1]) : "r"(a));
}
__device__ __forceinline__ void mma16816(float* c, const uint32_t* a, const uint32_t* b) {
    asm volatile("mma.sync.aligned.m16n8k16.row.col.f32.bf16.bf16.f32 "
        "{%0,%1,%2,%3}, {%4,%5,%6,%7}, {%8,%9}, {%0,%1,%2,%3};"
        : "+f"(c[0]), "+f"(c[1]), "+f"(c[2]), "+f"(c[3])
        : "r"(a[0]), "r"(a[1]), "r"(a[2]), "r"(a[3]), "r"(b[0]), "r"(b[1]));
}
__device__ __forceinline__ void sts32(uint32_t a, uint32_t v) {
    asm volatile("st.shared.b32 [%0], %1;" :: "r"(a), "r"(v) : "memory");
}
__device__ __forceinline__ void sts64(uint32_t a, uint32_t v0, uint32_t v1) {
    asm volatile("st.shared.v2.u32 [%0], {%1, %2};" :: "r"(a), "r"(v0), "r"(v1) : "memory");
}
__device__ __forceinline__ const unsigned char* chunk_src(int g) {
    int l = g & 31;
    return (l < 16) ? (g_Ub + (size_t)l * 32768) : (g_Wb + (size_t)(l - 16) * 32768);
}

// -------- prologue: fp32 -> bf16 SW128 tiles in gmem --------
__global__ void prep_uw_kernel(const float* __restrict__ U, const float* __restrict__ W) {
    int idx = blockIdx.x * blockDim.x + threadIdx.x;       // 262144
    if (idx < 131072) {
        int kc = idx >> 13, rem = idx & 8191, r = rem >> 5, j = rem & 31;
        float2 f = *(const float2*)(U + (size_t)r * DD + kc * 64 + j * 2);
        *(uint32_t*)(g_Ub + kc * 32768 + swz((uint32_t)(r * 128 + j * 4))) = bf2u(__float22bfloat162_rn(f));
    } else {
        int i2 = idx - 131072;
        int t = i2 >> 11, rem = i2 & 2047, dr = rem >> 5, j = rem & 31;
        int nc = t >> 2, kt = t & 3;
        float2 f = *(const float2*)(W + (size_t)(nc * 64 + dr) * RR + kt * 64 + j * 2);
        *(uint32_t*)(g_Wb + t * 8192 + swz((uint32_t)(dr * 128 + j * 4))) = bf2u(__float22bfloat162_rn(f));
    }
}

// -------- fused elementwise for one (row, col-pair) from fragment values --------
__device__ __forceinline__ void ew_pair(
    int r, int d, float g0, float g1, int c, int dl,
    int step, float dcoef, int row0,
    const float* __restrict__ x, const float* __restrict__ vsrc,
    const float* __restrict__ force, float* __restrict__ out, uint32_t SV)
{
    const size_t go = (size_t)(row0 + r) * DD + d;
    float2 f2 = *(const float2*)(force + go);
    float2 v2 = *(const float2*)(vsrc + go);
    float2 vn;
    vn.x = v2.x + dcoef * (f2.x - g0);
    vn.y = v2.y + dcoef * (f2.y - g1);
    *(float2*)(g_vf + go) = vn;
    sts32(SV + (uint32_t)c * 4096u + swz((uint32_t)(r * 128 + dl * 2)),
          bf2u(__float22bfloat162_rn(vn)));
    float2* ox = (float2*)(out + go);
    if (step == 0) {
        float2 t;
        t.x = K_C1f * v2.x + K_C2f * vn.x;
        t.y = K_C1f * v2.y + K_C2f * vn.y;
        *ox = t;
    } else if (step == 1) {
        float2 t = *ox;
        t.x += K_C2f * vn.x; t.y += K_C2f * vn.y;
        *ox = t;
    } else {
        float2 t = *ox;
        float2 x2 = *(const float2*)(x + go);
        t.x = x2.x + K_DT * (t.x + K_C1f * vn.x);
        t.y = x2.y + K_DT * (t.y + K_C1f * vn.y);
        *ox = t;
        *(float2*)(out + (size_t)BB * DD + go) = vn;
    }
}

// -------- main fused integrator: free-running warps --------
__global__ __launch_bounds__(NTHR, 1)
void yoshida_mma4_kernel(const float* __restrict__ x, const float* __restrict__ v,
                         const float* __restrict__ force, float* __restrict__ out) {
    extern __shared__ unsigned char dsm[];
    unsigned char* basep = (unsigned char*)(((uintptr_t)dsm + 1023u) & ~(uintptr_t)1023u);
    const uint32_t base = s2u(basep);
    const uint32_t SV   = base;                 // 64KB resident v bf16: 16 tiles [32 x 64] SW128
    const uint32_t RING = base + 65536u;        // 4 x 32KB unified U/W chunk ring
    const uint32_t H2   = base + 196608u;       // 4 x 4KB h^2 tiles [32 x 64] bf16 SW128
    const uint32_t BARS = base + 212992u;       // full[4] @ +0, cons[4] @ +32

    const int tid = threadIdx.x, wid = tid >> 5, lid = tid & 31;
    const int mh = wid >> 3;                   // M half: rows mh*16..+15
    const int q  = wid & 7;                    // N octant
    const int row0 = blockIdx.x * 32;

    const uint32_t arow  = (uint32_t)((mh * 16 + (lid & 15)) * 128 + ((lid >> 4) << 4));
    const uint32_t brow  = (uint32_t)(((lid & 7) + ((lid >> 4) << 3)) * 128 + (((lid >> 3) & 1) << 4));
    const uint32_t brow2 = (uint32_t)((lid & 7) * 128 + (((lid >> 3) & 1) << 4));
    const int hr = lid >> 2, hc2 = (lid & 3) * 2;

    if (tid == 0) {
        #pragma unroll
        for (int i = 0; i < 4; ++i) { mb_init(BARS + 8u * i, 1); mb_init(BARS + 32u + 8u * i, 16); }
        fence_async_sh();
        #pragma unroll
        for (int c = 0; c < 4; ++c) {
            mb_expect(BARS + 8u * c, 32768u);
            bulkcp(RING + (uint32_t)c * 32768u, chunk_src(c), 32768u, BARS + 8u * c);
        }
    }

    // resident sV init: bf16(v) pre-swizzled
    for (int i = tid; i < 8192; i += NTHR) {
        int row = i >> 8, rem = i & 255, kc = rem >> 4, jj = rem & 15;
        float4 f = *(const float4*)(v + (size_t)(row0 + row) * DD + kc * 64 + jj * 4);
        sts64(SV + (uint32_t)kc * 4096u + swz((uint32_t)(row * 128 + jj * 8)),
              bf2u(__float22bfloat162_rn(make_float2(f.x, f.y))),
              bf2u(__float22bfloat162_rn(make_float2(f.z, f.w))));
    }
    __syncthreads();

    const float dctab[3] = { (float)K_W1 * K_DT, (float)K_W0 * K_DT, (float)K_W1 * K_DT };
    const bool is_prod = (wid < 4) && (lid == 0);   // warp b owns buffer b's reissue
    uint32_t cph = 0;                                // producer's cons-phase tracker

    for (int step = 0; step < 3; ++step) {
        const float dcoef = dctab[step];
        const float* vsrc = (step == 0) ? v : g_vf;

        // ===== GEMM1: h[32 x 256] = sV @ U^T, K=1024 in 16 ring chunks (free-run) =====
        float acc1[4][4];
        #pragma unroll
        for (int t = 0; t < 4; ++t)
            #pragma unroll
            for (int j = 0; j < 4; ++j) acc1[t][j] = 0.f;

        for (int kc = 0; kc < 16; ++kc) {
            const int g = step * 32 + kc;
            const int b = g & 3;
            mb_wait(BARS + 8u * b, (uint32_t)((g >> 2) & 1));
            const uint32_t Ab = SV + (uint32_t)kc * 4096u;
            const uint32_t Bb = RING + (uint32_t)b * 32768u;
            #pragma unroll
            for (int ks = 0; ks < 4; ++ks) {
                uint32_t a[4];
                ldsm4(a, Ab + swz(arow + ks * 32));
                #pragma unroll
                for (int ntp = 0; ntp < 2; ++ntp) {
                    uint32_t bb[4];
                    ldsm4(bb, Bb + swz(brow + (uint32_t)((q * 32 + ntp * 16) * 128) + ks * 32));
                    mma16816(acc1[2 * ntp],     a, bb);
                    mma16816(acc1[2 * ntp + 1], a, bb + 2);
                }
            }
            if (lid == 0) mb_arrive(BARS + 32u + 8u * b);        // this warp done with buffer b
            if (is_prod && wid == b && g + 4 < 96) {             // buffer owner reissues
                mb_wait(BARS + 32u + 8u * b, cph); cph ^= 1;     // all 16 warps consumed
                mb_expect(BARS + 8u * b, 32768u);
                bulkcp(RING + (uint32_t)b * 32768u, chunk_src(g + 4), 32768u, BARS + 8u * b);
            }
        }

        // ---- h^2 -> bf16 SW128 H2 tiles ----
        {
            const uint32_t ht = H2 + (uint32_t)(q >> 1) * 4096u;
            #pragma unroll
            for (int t = 0; t < 4; ++t) {
                const int ntp = t >> 1, half = t & 1;
                float c0 = acc1[t][0], c1 = acc1[t][1], c2 = acc1[t][2], c3 = acc1[t][3];
                uint32_t p0 = bf2u(__float22bfloat162_rn(make_float2(c0 * c0, c1 * c1)));
                uint32_t p1 = bf2u(__float22bfloat162_rn(make_float2(c2 * c2, c3 * c3)));
                uint32_t koff = (uint32_t)(((q & 1) * 32 + ntp * 16 + half * 8 + hc2) * 2);
                sts32(ht + swz((uint32_t)((mh * 16 + hr) * 128) + koff), p0);
                sts32(ht + swz((uint32_t)((mh * 16 + hr + 8) * 128) + koff), p1);
            }
        }
        __syncthreads();    // H2 complete before any GEMM2 read

        // ===== GEMM2: Gamma = h2 @ W^T, 16 n-chunks of 64, fused update (free-run) =====
        for (int it = 0; it < 16; ++it) {
            const int g = step * 32 + 16 + it;
            const int b = g & 3;
            float acc2[4] = {0.f, 0.f, 0.f, 0.f};
            mb_wait(BARS + 8u * b, (uint32_t)((g >> 2) & 1));
            const uint32_t Bc = RING + (uint32_t)b * 32768u + (uint32_t)q * 1024u;
            #pragma unroll
            for (int kt = 0; kt < 4; ++kt) {
                const uint32_t At = H2 + (uint32_t)kt * 4096u;
                const uint32_t Bt = Bc + (uint32_t)kt * 8192u;
                #pragma unroll
                for (int ks = 0; ks < 4; ++ks) {
                    uint32_t a[4], b2[2];
                    ldsm4(a,  At + swz(arow + ks * 32));
                    ldsm2(b2, Bt + swz(brow2 + ks * 32));
                    mma16816(acc2, a, b2);
                }
            }
            if (lid == 0) mb_arrive(BARS + 32u + 8u * b);
            if (is_prod && wid == b && g + 4 < 96) {
                mb_wait(BARS + 32u + 8u * b, cph); cph ^= 1;
                mb_expect(BARS + 8u * b, 32768u);
                bulkcp(RING + (uint32_t)b * 32768u, chunk_src(g + 4), 32768u, BARS + 8u * b);
            }
            // elementwise directly from fragments (rows mh*16+hr, +8; cols q*8+hc2,+1)
            const int dl = q * 8 + hc2;
            const int d = it * 64 + dl;
            ew_pair(mh * 16 + hr,     d, acc2[0], acc2[1], it, dl, step, dcoef, row0, x, vsrc, force, out, SV);
            ew_pair(mh * 16 + hr + 8, d, acc2[2], acc2[3], it, dl, step, dcoef, row0, x, vsrc, force, out, SV);
        }
        __syncthreads();    // SV fully updated before next step's GEMM1 reads
    }
}

extern "C" void kernel_launch(void* const* d_in, const int* in_sizes, int n_in,
                              void* d_out, int out_size)
{
    const float* x     = (const float*)d_in[0];
    const float* v     = (const float*)d_in[1];
    const float* force = (const float*)d_in[2];
    const float* U     = (const float*)d_in[3];
    const float* W     = (const float*)d_in[4];
    float* out = (float*)d_out;

    const int smem_bytes = 214080;
    cudaFuncSetAttribute(yoshida_mma4_kernel, cudaFuncAttributeMaxDynamicSharedMemorySize, smem_bytes);

    prep_uw_kernel<<<1024, 256>>>(U, W);
    yoshida_mma4_kernel<<<NCTA, NTHR, smem_bytes>>>(x, v, force, out);
}

// round 8
// speedup vs baseline: 1.2215x; 1.2215x over previous
#include <cuda_runtime.h>
#include <cuda_bf16.h>
#include <stdint.h>

#define BB 4096
#define DD 1024
#define RR 256
#define NCTA 128
#define NTHR 512

#define K_W1 1.3512071919596578
#define K_W0 (-1.7024143839193153)
#define K_C1f ((float)(K_W1 * 0.5))
#define K_C2f ((float)((K_W0 + K_W1) * 0.5))
#define K_DT 0.01f

// -------- device-global scratch (no runtime allocation) --------
__device__ __align__(1024) unsigned char g_Ub[16 * 32768];   // U bf16: 16 k-chunks [256n x 64k] SW128
__device__ __align__(1024) unsigned char g_Wb[64 * 8192];    // W bf16: 16 n-chunks x 4 k-tiles [64n x 64k] SW128
__device__ __align__(1024) float g_vf[(size_t)BB * DD];      // v fp32 master

// -------- helpers --------
__device__ __forceinline__ uint32_t swz(uint32_t o) { return o ^ ((o >> 3) & 0x70); }
__device__ __forceinline__ uint32_t s2u(const void* p) {
    uint32_t a; asm("{ .reg .u64 t; cvta.to.shared.u64 t, %1; cvt.u32.u64 %0, t; }" : "=r"(a) : "l"(p)); return a;
}
__device__ __forceinline__ uint32_t bf2u(__nv_bfloat162 b) { return *reinterpret_cast<uint32_t*>(&b); }
__device__ __forceinline__ void mb_init(uint32_t a, uint32_t c) {
    asm volatile("mbarrier.init.shared.b64 [%0], %1;" :: "r"(a), "r"(c) : "memory");
}
__device__ __forceinline__ void mb_expect(uint32_t a, uint32_t b) {
    asm volatile("mbarrier.arrive.expect_tx.shared.b64 _, [%0], %1;" :: "r"(a), "r"(b) : "memory");
}
__device__ __forceinline__ void mb_wait(uint32_t a, uint32_t p) {
    asm volatile("{\n\t.reg .pred P;\n\tLW%=:\n\t"
        "mbarrier.try_wait.parity.acquire.cta.shared::cta.b64 P, [%0], %1, 0x989680;\n\t"
        "@P bra LD%=;\n\tbra LW%=;\n\tLD%=:\n\t}" :: "r"(a), "r"(p) : "memory");
}
__device__ __forceinline__ void bulkcp(uint32_t d, const void* s, uint32_t n, uint32_t mb) {
    asm volatile("cp.async.bulk.shared::cluster.global.mbarrier::complete_tx::bytes [%0], [%1], %2, [%3];"
                 :: "r"(d), "l"(s), "r"(n), "r"(mb) : "memory");
}
__device__ __forceinline__ void fence_async_sh() { asm volatile("fence.proxy.async.shared::cta;" ::: "memory"); }
__device__ __forceinline__ void ldsm4(uint32_t* r, uint32_t a) {
    asm volatile("ldmatrix.sync.aligned.m8n8.x4.shared.b16 {%0,%1,%2,%3}, [%4];"
                 : "=r"(r[0]), "=r"(r[1]), "=r"(r[2]), "=r"(r[3]) : "r"(a));
}
__device__ __forceinline__ void mma16816(float* c, const uint32_t* a, const uint32_t* b) {
    asm volatile("mma.sync.aligned.m16n8k16.row.col.f32.bf16.bf16.f32 "
        "{%0,%1,%2,%3}, {%4,%5,%6,%7}, {%8,%9}, {%0,%1,%2,%3};"
        : "+f"(c[0]), "+f"(c[1]), "+f"(c[2]), "+f"(c[3])
        : "r"(a[0]), "r"(a[1]), "r"(a[2]), "r"(a[3]), "r"(b[0]), "r"(b[1]));
}
__device__ __forceinline__ void sts32(uint32_t a, uint32_t v) {
    asm volatile("st.shared.b32 [%0], %1;" :: "r"(a), "r"(v) : "memory");
}
__device__ __forceinline__ void sts64(uint32_t a, uint32_t v0, uint32_t v1) {
    asm volatile("st.shared.v2.u32 [%0], {%1, %2};" :: "r"(a), "r"(v0), "r"(v1) : "memory");
}
__device__ __forceinline__ const unsigned char* chunk_src(int g) {
    int l = g & 31;
    return (l < 16) ? (g_Ub + (size_t)l * 32768) : (g_Wb + (size_t)(l - 16) * 32768);
}

// -------- prologue: fp32 -> bf16 SW128 tiles in gmem --------
__global__ void prep_uw_kernel(const float* __restrict__ U, const float* __restrict__ W) {
    int idx = blockIdx.x * blockDim.x + threadIdx.x;       // 262144
    if (idx < 131072) {
        int kc = idx >> 13, rem = idx & 8191, r = rem >> 5, j = rem & 31;
        float2 f = *(const float2*)(U + (size_t)r * DD + kc * 64 + j * 2);
        *(uint32_t*)(g_Ub + kc * 32768 + swz((uint32_t)(r * 128 + j * 4))) = bf2u(__float22bfloat162_rn(f));
    } else {
        int i2 = idx - 131072;
        int t = i2 >> 11, rem = i2 & 2047, dr = rem >> 5, j = rem & 31;
        int nc = t >> 2, kt = t & 3;
        float2 f = *(const float2*)(W + (size_t)(nc * 64 + dr) * RR + kt * 64 + j * 2);
        *(uint32_t*)(g_Wb + t * 8192 + swz((uint32_t)(dr * 128 + j * 4))) = bf2u(__float22bfloat162_rn(f));
    }
}

// -------- fused elementwise for one float4 at (er, chunk cc, in-chunk col dl) --------
__device__ __forceinline__ void ew_f4(
    int cc, int dl, const float* sgp, int step, float dcoef,
    const float* __restrict__ x, const float* __restrict__ vsrc,
    const float* __restrict__ force, float* __restrict__ out,
    uint32_t SV, int er, size_t grow)
{
    const int d = cc * 64 + dl;
    float4 g4 = *(const float4*)sgp;
    float4 f4 = *(const float4*)(force + grow + d);
    float4 v4 = *(const float4*)(vsrc + grow + d);
    float4 vn;
    vn.x = v4.x + dcoef * (f4.x - g4.x);
    vn.y = v4.y + dcoef * (f4.y - g4.y);
    vn.z = v4.z + dcoef * (f4.z - g4.z);
    vn.w = v4.w + dcoef * (f4.w - g4.w);
    *(float4*)(g_vf + grow + d) = vn;
    sts64(SV + (uint32_t)cc * 4096u + swz((uint32_t)(er * 128 + dl * 2)),
          bf2u(__float22bfloat162_rn(make_float2(vn.x, vn.y))),
          bf2u(__float22bfloat162_rn(make_float2(vn.z, vn.w))));
    float4* ox = (float4*)(out + grow + d);
    if (step == 0) {
        float4 t;
        t.x = K_C1f * v4.x + K_C2f * vn.x; t.y = K_C1f * v4.y + K_C2f * vn.y;
        t.z = K_C1f * v4.z + K_C2f * vn.z; t.w = K_C1f * v4.w + K_C2f * vn.w;
        *ox = t;
    } else if (step == 1) {
        float4 t = *ox;
        t.x += K_C2f * vn.x; t.y += K_C2f * vn.y;
        t.z += K_C2f * vn.z; t.w += K_C2f * vn.w;
        *ox = t;
    } else {
        float4 t = *ox;
        float4 x4 = *(const float4*)(x + grow + d);
        t.x = x4.x + K_DT * (t.x + K_C1f * vn.x);
        t.y = x4.y + K_DT * (t.y + K_C1f * vn.y);
        t.z = x4.z + K_DT * (t.z + K_C1f * vn.z);
        t.w = x4.w + K_DT * (t.w + K_C1f * vn.w);
        *ox = t;
        *(float4*)(out + (size_t)BB * DD + grow + d) = vn;
    }
}

// -------- main fused integrator --------
__global__ __launch_bounds__(NTHR, 1)
void yoshida_mma5_kernel(const float* __restrict__ x, const float* __restrict__ v,
                         const float* __restrict__ force, float* __restrict__ out) {
    extern __shared__ unsigned char dsm[];
    unsigned char* basep = (unsigned char*)(((uintptr_t)dsm + 1023u) & ~(uintptr_t)1023u);
    const uint32_t base = s2u(basep);
    const uint32_t SV   = base;                 // 64KB resident v bf16: 16 tiles [32 x 64] SW128
    const uint32_t RING = base + 65536u;        // 4 x 32KB unified U/W chunk ring
    const uint32_t H2   = base + 196608u;       // 4 x 4KB h^2 tiles [32 x 64] bf16 SW128
    float* SGf = (float*)(basep + 212992u);     // sGamma pair buffer [32][132] f32 (16896B)
    const uint32_t BARS = base + 229888u;       // full[4]

    const int tid = threadIdx.x, wid = tid >> 5, lid = tid & 31;
    const int mh = wid >> 3;                   // GEMM1 M half
    const int q  = wid & 7;                    // GEMM1 N octant
    const int quad = wid & 3;                  // GEMM2: ring-buffer / chunk owner
    const int w4 = wid >> 2;
    const int mh2 = w4 & 1;                    // GEMM2 M half
    const int nn  = w4 >> 1;                   // GEMM2 N 32-half within chunk
    const int row0 = blockIdx.x * 32;

    const uint32_t arow  = (uint32_t)((mh  * 16 + (lid & 15)) * 128 + ((lid >> 4) << 4));
    const uint32_t arow2 = (uint32_t)((mh2 * 16 + (lid & 15)) * 128 + ((lid >> 4) << 4));
    const uint32_t brow  = (uint32_t)(((lid & 7) + ((lid >> 4) << 3)) * 128 + (((lid >> 3) & 1) << 4));
    const int hr = lid >> 2, hc2 = (lid & 3) * 2;
    const int er = tid >> 4, el = (tid & 15) * 8;       // ew: row, col-base (2 float4)
    const size_t grow = (size_t)(row0 + er) * DD;

    if (tid == 0) {
        #pragma unroll
        for (int i = 0; i < 4; ++i) mb_init(BARS + 8u * i, 1);
        fence_async_sh();
        #pragma unroll
        for (int c = 0; c < 4; ++c) {
            mb_expect(BARS + 8u * c, 32768u);
            bulkcp(RING + (uint32_t)c * 32768u, chunk_src(c), 32768u, BARS + 8u * c);
        }
    }

    // resident sV init: bf16(v) pre-swizzled
    for (int i = tid; i < 8192; i += NTHR) {
        int row = i >> 8, rem = i & 255, kc = rem >> 4, jj = rem & 15;
        float4 f = *(const float4*)(v + (size_t)(row0 + row) * DD + kc * 64 + jj * 4);
        sts64(SV + (uint32_t)kc * 4096u + swz((uint32_t)(row * 128 + jj * 8)),
              bf2u(__float22bfloat162_rn(make_float2(f.x, f.y))),
              bf2u(__float22bfloat162_rn(make_float2(f.z, f.w))));
    }
    __syncthreads();

    const float dctab[3] = { (float)K_W1 * K_DT, (float)K_W0 * K_DT, (float)K_W1 * K_DT };

    for (int step = 0; step < 3; ++step) {
        const float dcoef = dctab[step];
        const float* vsrc = (step == 0) ? v : g_vf;

        // ===== GEMM1: h[32 x 256] = sV @ U^T, K=1024 in 16 ring chunks (R6 structure) =====
        float acc1[4][4];
        #pragma unroll
        for (int t = 0; t < 4; ++t)
            #pragma unroll
            for (int j = 0; j < 4; ++j) acc1[t][j] = 0.f;

        for (int kc = 0; kc < 16; ++kc) {
            const int g = step * 32 + kc;
            const int b = g & 3;
            mb_wait(BARS + 8u * b, (uint32_t)((g >> 2) & 1));
            const uint32_t Ab = SV + (uint32_t)kc * 4096u;
            const uint32_t Bb = RING + (uint32_t)b * 32768u;
            #pragma unroll
            for (int ks = 0; ks < 4; ++ks) {
                uint32_t a[4];
                ldsm4(a, Ab + swz(arow + ks * 32));
                #pragma unroll
                for (int ntp = 0; ntp < 2; ++ntp) {
                    uint32_t bb[4];
                    ldsm4(bb, Bb + swz(brow + (uint32_t)((q * 32 + ntp * 16) * 128) + ks * 32));
                    mma16816(acc1[2 * ntp],     a, bb);
                    mma16816(acc1[2 * ntp + 1], a, bb + 2);
                }
            }
            __syncthreads();
            if (tid == 0 && g + 4 < 96) {
                mb_expect(BARS + 8u * b, 32768u);
                bulkcp(RING + (uint32_t)b * 32768u, chunk_src(g + 4), 32768u, BARS + 8u * b);
            }
        }

        // ---- h^2 -> bf16 SW128 H2 tiles ----
        {
            const uint32_t ht = H2 + (uint32_t)(q >> 1) * 4096u;
            #pragma unroll
            for (int t = 0; t < 4; ++t) {
                const int ntp = t >> 1, half = t & 1;
                float c0 = acc1[t][0], c1 = acc1[t][1], c2 = acc1[t][2], c3 = acc1[t][3];
                uint32_t p0 = bf2u(__float22bfloat162_rn(make_float2(c0 * c0, c1 * c1)));
                uint32_t p1 = bf2u(__float22bfloat162_rn(make_float2(c2 * c2, c3 * c3)));
                uint32_t koff = (uint32_t)(((q & 1) * 32 + ntp * 16 + half * 8 + hc2) * 2);
                sts32(ht + swz((uint32_t)((mh * 16 + hr) * 128) + koff), p0);
                sts32(ht + swz((uint32_t)((mh * 16 + hr + 8) * 128) + koff), p1);
            }
        }
        __syncthreads();    // H2 complete before any GEMM2 read

        // ===== GEMM2: quad-grouped — 4 groups x 4 concurrent chunks, A-fragments reused 4x =====
        for (int g4 = 0; g4 < 4; ++g4) {
            const int c = g4 * 4 + quad;                 // this warp's chunk
            const int g = step * 32 + 16 + c;
            mb_wait(BARS + 8u * quad, (uint32_t)((g >> 2) & 1));

            float acc2[4][4];
            #pragma unroll
            for (int t = 0; t < 4; ++t)
                #pragma unroll
                for (int j = 0; j < 4; ++j) acc2[t][j] = 0.f;

            const uint32_t Bb = RING + (uint32_t)quad * 32768u;
            #pragma unroll
            for (int kt = 0; kt < 4; ++kt) {
                const uint32_t At = H2 + (uint32_t)kt * 4096u;
                const uint32_t Bt = Bb + (uint32_t)kt * 8192u;
                #pragma unroll
                for (int ks = 0; ks < 4; ++ks) {
                    uint32_t a[4];
                    ldsm4(a, At + swz(arow2 + ks * 32));
                    #pragma unroll
                    for (int ntp = 0; ntp < 2; ++ntp) {
                        uint32_t bb[4];
                        ldsm4(bb, Bt + swz(brow + (uint32_t)((nn * 32 + ntp * 16) * 128) + ks * 32));
                        mma16816(acc2[2 * ntp],     a, bb);
                        mma16816(acc2[2 * ntp + 1], a, bb + 2);
                    }
                }
            }
            __syncthreads();                             // all 4 buffers consumed by all warps
            if (tid == 0) {                              // batch-refill all 4 buffers (overlaps ew)
                #pragma unroll
                for (int b = 0; b < 4; ++b) {
                    const int gn = step * 32 + 16 + g4 * 4 + b + 4;
                    if (gn < 96) {
                        mb_expect(BARS + 8u * b, 32768u);
                        bulkcp(RING + (uint32_t)b * 32768u, chunk_src(gn), 32768u, BARS + 8u * b);
                    }
                }
            }

            // two staging pairs: chunks {g4*4+0, +1} then {+2, +3}
            #pragma unroll
            for (int p = 0; p < 2; ++p) {
                if ((quad >> 1) == p) {                  // quads 2p, 2p+1 stage their chunk
                    const int sgc = (quad & 1) * 64 + nn * 32;
                    #pragma unroll
                    for (int t = 0; t < 4; ++t) {
                        const int col = sgc + t * 8 + hc2;
                        *(float2*)(SGf + (mh2 * 16 + hr) * 132 + col)     = make_float2(acc2[t][0], acc2[t][1]);
                        *(float2*)(SGf + (mh2 * 16 + hr + 8) * 132 + col) = make_float2(acc2[t][2], acc2[t][3]);
                    }
                }
                __syncthreads();
                // coalesced ew over the 128-col pair (2 float4 per thread)
                {
                    const int cc0 = g4 * 4 + 2 * p + (el >> 6);
                    const int dl0 = el & 63;
                    ew_f4(cc0, dl0, SGf + er * 132 + el, step, dcoef, x, vsrc, force, out, SV, er, grow);
                    const int el1 = el + 4;
                    const int cc1 = g4 * 4 + 2 * p + (el1 >> 6);
                    ew_f4(cc1, el1 & 63, SGf + er * 132 + el1, step, dcoef, x, vsrc, force, out, SV, er, grow);
                }
                if (p == 0) __syncthreads();             // ew reads done before pair-1 overwrites SG
            }
        }
        __syncthreads();    // SV fully updated before next step's GEMM1 reads
    }
}

extern "C" void kernel_launch(void* const* d_in, const int* in_sizes, int n_in,
                              void* d_out, int out_size)
{
    const float* x     = (const float*)d_in[0];
    const float* v     = (const float*)d_in[1];
    const float* force = (const float*)d_in[2];
    const float* U     = (const float*)d_in[3];
    const float* W     = (const float*)d_in[4];
    float* out = (float*)d_out;

    const int smem_bytes = 230976;
    cudaFuncSetAttribute(yoshida_mma5_kernel, cudaFuncAttributeMaxDynamicSharedMemorySize, smem_bytes);

    prep_uw_kernel<<<1024, 256>>>(U, W);
    yoshida_mma5_kernel<<<NCTA, NTHR, smem_bytes>>>(x, v, force, out);
}

// round 9
// speedup vs baseline: 1.4700x; 1.2034x over previous
#include <cuda_runtime.h>
#include <cuda_bf16.h>
#include <stdint.h>

#define BB 4096
#define DD 1024
#define RR 256
#define NCTA 128
#define NTHR 512

#define K_W1 1.3512071919596578
#define K_W0 (-1.7024143839193153)
#define K_C1f ((float)(K_W1 * 0.5))
#define K_C2f ((float)((K_W0 + K_W1) * 0.5))
#define K_DT 0.01f

// -------- device-global scratch (no runtime allocation) --------
__device__ __align__(1024) unsigned char g_Ub[16 * 32768];   // U bf16: 16 k-chunks [256n x 64k] SW128
__device__ __align__(1024) unsigned char g_Wb[64 * 8192];    // W bf16: 16 n-chunks x 4 k-tiles [64n x 64k] SW128
__device__ __align__(1024) float g_vf[(size_t)BB * DD];      // v fp32 master

// -------- helpers --------
__device__ __forceinline__ uint32_t swz(uint32_t o) { return o ^ ((o >> 3) & 0x70); }
__device__ __forceinline__ uint32_t s2u(const void* p) {
    uint32_t a; asm("{ .reg .u64 t; cvta.to.shared.u64 t, %1; cvt.u32.u64 %0, t; }" : "=r"(a) : "l"(p)); return a;
}
__device__ __forceinline__ uint32_t bf2u(__nv_bfloat162 b) { return *reinterpret_cast<uint32_t*>(&b); }
__device__ __forceinline__ void mb_init(uint32_t a, uint32_t c) {
    asm volatile("mbarrier.init.shared.b64 [%0], %1;" :: "r"(a), "r"(c) : "memory");
}
__device__ __forceinline__ void mb_expect(uint32_t a, uint32_t b) {
    asm volatile("mbarrier.arrive.expect_tx.shared.b64 _, [%0], %1;" :: "r"(a), "r"(b) : "memory");
}
__device__ __forceinline__ void mb_wait(uint32_t a, uint32_t p) {
    asm volatile("{\n\t.reg .pred P;\n\tLW%=:\n\t"
        "mbarrier.try_wait.parity.acquire.cta.shared::cta.b64 P, [%0], %1, 0x989680;\n\t"
        "@P bra LD%=;\n\tbra LW%=;\n\tLD%=:\n\t}" :: "r"(a), "r"(p) : "memory");
}
__device__ __forceinline__ void bulkcp(uint32_t d, const void* s, uint32_t n, uint32_t mb) {
    asm volatile("cp.async.bulk.shared::cluster.global.mbarrier::complete_tx::bytes [%0], [%1], %2, [%3];"
                 :: "r"(d), "l"(s), "r"(n), "r"(mb) : "memory");
}
__device__ __forceinline__ void fence_async_sh() { asm volatile("fence.proxy.async.shared::cta;" ::: "memory"); }
__device__ __forceinline__ void ldsm4(uint32_t* r, uint32_t a) {
    asm volatile("ldmatrix.sync.aligned.m8n8.x4.shared.b16 {%0,%1,%2,%3}, [%4];"
                 : "=r"(r[0]), "=r"(r[1]), "=r"(r[2]), "=r"(r[3]) : "r"(a));
}
__device__ __forceinline__ void mma16816(float* c, const uint32_t* a, const uint32_t* b) {
    asm volatile("mma.sync.aligned.m16n8k16.row.col.f32.bf16.bf16.f32 "
        "{%0,%1,%2,%3}, {%4,%5,%6,%7}, {%8,%9}, {%0,%1,%2,%3};"
        : "+f"(c[0]), "+f"(c[1]), "+f"(c[2]), "+f"(c[3])
        : "r"(a[0]), "r"(a[1]), "r"(a[2]), "r"(a[3]), "r"(b[0]), "r"(b[1]));
}
__device__ __forceinline__ void sts32(uint32_t a, uint32_t v) {
    asm volatile("st.shared.b32 [%0], %1;" :: "r"(a), "r"(v) : "memory");
}
__device__ __forceinline__ void sts64(uint32_t a, uint32_t v0, uint32_t v1) {
    asm volatile("st.shared.v2.u32 [%0], {%1, %2};" :: "r"(a), "r"(v0), "r"(v1) : "memory");
}
__device__ __forceinline__ const unsigned char* chunk_src(int g) {
    int l = g & 31;
    return (l < 16) ? (g_Ub + (size_t)l * 32768) : (g_Wb + (size_t)(l - 16) * 32768);
}

// -------- prologue: fp32 -> bf16 SW128 tiles in gmem --------
__global__ void prep_uw_kernel(const float* __restrict__ U, const float* __restrict__ W) {
    int idx = blockIdx.x * blockDim.x + threadIdx.x;       // 262144
    if (idx < 131072) {
        int kc = idx >> 13, rem = idx & 8191, r = rem >> 5, j = rem & 31;
        float2 f = *(const float2*)(U + (size_t)r * DD + kc * 64 + j * 2);
        *(uint32_t*)(g_Ub + kc * 32768 + swz((uint32_t)(r * 128 + j * 4))) = bf2u(__float22bfloat162_rn(f));
    } else {
        int i2 = idx - 131072;
        int t = i2 >> 11, rem = i2 & 2047, dr = rem >> 5, j = rem & 31;
        int nc = t >> 2, kt = t & 3;
        float2 f = *(const float2*)(W + (size_t)(nc * 64 + dr) * RR + kt * 64 + j * 2);
        *(uint32_t*)(g_Wb + t * 8192 + swz((uint32_t)(dr * 128 + j * 4))) = bf2u(__float22bfloat162_rn(f));
    }
}

// -------- main fused integrator --------
__global__ __launch_bounds__(NTHR, 1)
void yoshida_mma6_kernel(const float* __restrict__ x, const float* __restrict__ v,
                         const float* __restrict__ force, float* __restrict__ out) {
    extern __shared__ unsigned char dsm[];
    unsigned char* basep = (unsigned char*)(((uintptr_t)dsm + 1023u) & ~(uintptr_t)1023u);
    const uint32_t base = s2u(basep);
    const uint32_t SV   = base;                 // 64KB resident v bf16: 16 tiles [32 x 64] SW128
    const uint32_t RING = base + 65536u;        // 4 x 32KB unified U/W chunk ring
    const uint32_t H2   = base + 196608u;       // 4 x 4KB h^2 tiles [32 x 64] bf16 SW128
    unsigned char* SGB  = basep + 212992u;      // sGamma bf16 [32][264] (16896 B)
    const uint32_t SGBu = base + 212992u;
    const uint32_t BARS = base + 229888u;       // full[4]

    const int tid = threadIdx.x, wid = tid >> 5, lid = tid & 31;
    const int mh = wid >> 3;                   // GEMM1 M half
    const int q  = wid & 7;                    // GEMM1 N octant
    const int quad = wid & 3;                  // GEMM2: ring-buffer / chunk owner
    const int w4 = wid >> 2;
    const int mh2 = w4 & 1;                    // GEMM2 M half
    const int nn  = w4 >> 1;                   // GEMM2 N 32-half within chunk
    const int row0 = blockIdx.x * 32;

    const uint32_t arow  = (uint32_t)((mh  * 16 + (lid & 15)) * 128 + ((lid >> 4) << 4));
    const uint32_t arow2 = (uint32_t)((mh2 * 16 + (lid & 15)) * 128 + ((lid >> 4) << 4));
    const uint32_t brow  = (uint32_t)(((lid & 7) + ((lid >> 4) << 3)) * 128 + (((lid >> 3) & 1) << 4));
    const int hr = lid >> 2, hc2 = (lid & 3) * 2;
    const int er = tid >> 4, el4 = (tid & 15) * 4;      // ew: row, col-base within 64
    const size_t grow = (size_t)(row0 + er) * DD;

    if (tid == 0) {
        #pragma unroll
        for (int i = 0; i < 4; ++i) mb_init(BARS + 8u * i, 1);
        fence_async_sh();
        #pragma unroll
        for (int c = 0; c < 4; ++c) {
            mb_expect(BARS + 8u * c, 32768u);
            bulkcp(RING + (uint32_t)c * 32768u, chunk_src(c), 32768u, BARS + 8u * c);
        }
    }

    // resident sV init: bf16(v) pre-swizzled
    for (int i = tid; i < 8192; i += NTHR) {
        int row = i >> 8, rem = i & 255, kc = rem >> 4, jj = rem & 15;
        float4 f = *(const float4*)(v + (size_t)(row0 + row) * DD + kc * 64 + jj * 4);
        sts64(SV + (uint32_t)kc * 4096u + swz((uint32_t)(row * 128 + jj * 8)),
              bf2u(__float22bfloat162_rn(make_float2(f.x, f.y))),
              bf2u(__float22bfloat162_rn(make_float2(f.z, f.w))));
    }
    __syncthreads();

    const float dctab[3] = { (float)K_W1 * K_DT, (float)K_W0 * K_DT, (float)K_W1 * K_DT };

    for (int step = 0; step < 3; ++step) {
        const float dcoef = dctab[step];
        const float* vsrc = (step == 0) ? v : g_vf;

        // ===== GEMM1: h[32 x 256] = sV @ U^T, 8 chunk-PAIRS (2 chunks per sync) =====
        float acc1[4][4];
        #pragma unroll
        for (int t = 0; t < 4; ++t)
            #pragma unroll
            for (int j = 0; j < 4; ++j) acc1[t][j] = 0.f;

        for (int kp = 0; kp < 8; ++kp) {
            const int g = step * 32 + kp * 2;          // even; g, g+1 in same 4-group
            const int b0 = g & 3;
            const uint32_t ph = (uint32_t)((g >> 2) & 1);
            mb_wait(BARS + 8u * b0, ph);
            mb_wait(BARS + 8u * (b0 + 1), ph);
            #pragma unroll
            for (int cc = 0; cc < 2; ++cc) {
                const uint32_t Ab = SV + (uint32_t)(kp * 2 + cc) * 4096u;
                const uint32_t Bb = RING + (uint32_t)(b0 + cc) * 32768u;
                #pragma unroll
                for (int ks = 0; ks < 4; ++ks) {
                    uint32_t a[4];
                    ldsm4(a, Ab + swz(arow + ks * 32));
                    #pragma unroll
                    for (int ntp = 0; ntp < 2; ++ntp) {
                        uint32_t bb[4];
                        ldsm4(bb, Bb + swz(brow + (uint32_t)((q * 32 + ntp * 16) * 128) + ks * 32));
                        mma16816(acc1[2 * ntp],     a, bb);
                        mma16816(acc1[2 * ntp + 1], a, bb + 2);
                    }
                }
            }
            __syncthreads();
            if (tid == 0) {                            // refill both buffers (chunks g+4, g+5)
                if (g + 4 < 96) {
                    mb_expect(BARS + 8u * b0, 32768u);
                    bulkcp(RING + (uint32_t)b0 * 32768u, chunk_src(g + 4), 32768u, BARS + 8u * b0);
                }
                if (g + 5 < 96) {
                    mb_expect(BARS + 8u * (b0 + 1), 32768u);
                    bulkcp(RING + (uint32_t)(b0 + 1) * 32768u, chunk_src(g + 5), 32768u, BARS + 8u * (b0 + 1));
                }
            }
        }

        // ---- h^2 -> bf16 SW128 H2 tiles ----
        {
            const uint32_t ht = H2 + (uint32_t)(q >> 1) * 4096u;
            #pragma unroll
            for (int t = 0; t < 4; ++t) {
                const int ntp = t >> 1, half = t & 1;
                float c0 = acc1[t][0], c1 = acc1[t][1], c2 = acc1[t][2], c3 = acc1[t][3];
                uint32_t p0 = bf2u(__float22bfloat162_rn(make_float2(c0 * c0, c1 * c1)));
                uint32_t p1 = bf2u(__float22bfloat162_rn(make_float2(c2 * c2, c3 * c3)));
                uint32_t koff = (uint32_t)(((q & 1) * 32 + ntp * 16 + half * 8 + hc2) * 2);
                sts32(ht + swz((uint32_t)((mh * 16 + hr) * 128) + koff), p0);
                sts32(ht + swz((uint32_t)((mh * 16 + hr + 8) * 128) + koff), p1);
            }
        }
        __syncthreads();    // H2 complete before any GEMM2 read

        // ===== GEMM2: quad-grouped, 4 groups x 4 chunks; single-shot bf16 staging =====
        for (int g4 = 0; g4 < 4; ++g4) {
            const int g = step * 32 + 16 + g4 * 4 + quad;
            mb_wait(BARS + 8u * quad, (uint32_t)((g >> 2) & 1));

            float acc2[4][4];
            #pragma unroll
            for (int t = 0; t < 4; ++t)
                #pragma unroll
                for (int j = 0; j < 4; ++j) acc2[t][j] = 0.f;

            const uint32_t Bb = RING + (uint32_t)quad * 32768u;
            #pragma unroll
            for (int kt = 0; kt < 4; ++kt) {
                const uint32_t At = H2 + (uint32_t)kt * 4096u;
                const uint32_t Bt = Bb + (uint32_t)kt * 8192u;
                #pragma unroll
                for (int ks = 0; ks < 4; ++ks) {
                    uint32_t a[4];
                    ldsm4(a, At + swz(arow2 + ks * 32));
                    #pragma unroll
                    for (int ntp = 0; ntp < 2; ++ntp) {
                        uint32_t bb[4];
                        ldsm4(bb, Bt + swz(brow + (uint32_t)((nn * 32 + ntp * 16) * 128) + ks * 32));
                        mma16816(acc2[2 * ntp],     a, bb);
                        mma16816(acc2[2 * ntp + 1], a, bb + 2);
                    }
                }
            }
            __syncthreads();                           // all 4 buffers consumed
            if (tid == 0) {                            // batch-refill (overlaps staging+ew)
                #pragma unroll
                for (int b = 0; b < 4; ++b) {
                    const int gn = step * 32 + 16 + g4 * 4 + b + 4;
                    if (gn < 96) {
                        mb_expect(BARS + 8u * b, 32768u);
                        bulkcp(RING + (uint32_t)b * 32768u, chunk_src(gn), 32768u, BARS + 8u * b);
                    }
                }
            }

            // single-shot staging: every warp stages its chunk's 64 cols (bf16)
            {
                const int colb = quad * 64 + nn * 32;
                const uint32_t r0 = (uint32_t)((mh2 * 16 + hr) * 528);
                #pragma unroll
                for (int t = 0; t < 4; ++t) {
                    const uint32_t co = (uint32_t)((colb + t * 8 + hc2) * 2);
                    sts32(SGBu + r0 + co,
                          bf2u(__float22bfloat162_rn(make_float2(acc2[t][0], acc2[t][1]))));
                    sts32(SGBu + r0 + 8u * 528u + co,
                          bf2u(__float22bfloat162_rn(make_float2(acc2[t][2], acc2[t][3]))));
                }
            }
            __syncthreads();

            // coalesced ew over all 256 cols: 4 float4 per thread at cols el4 + i*64
            {
                const __nv_bfloat162* sgr = (const __nv_bfloat162*)(SGB + (size_t)er * 528 + (size_t)el4 * 2);
                #pragma unroll
                for (int i = 0; i < 4; ++i) {
                    float2 ga = __bfloat1622float2(sgr[i * 32]);
                    float2 gb = __bfloat1622float2(sgr[i * 32 + 1]);
                    const int d = g4 * 256 + el4 + i * 64;
                    const int cc = d >> 6, dl = d & 63;
                    float4 f4 = *(const float4*)(force + grow + d);
                    float4 v4 = *(const float4*)(vsrc + grow + d);
                    float4 vn;
                    vn.x = v4.x + dcoef * (f4.x - ga.x);
                    vn.y = v4.y + dcoef * (f4.y - ga.y);
                    vn.z = v4.z + dcoef * (f4.z - gb.x);
                    vn.w = v4.w + dcoef * (f4.w - gb.y);
                    *(float4*)(g_vf + grow + d) = vn;
                    sts64(SV + (uint32_t)cc * 4096u + swz((uint32_t)(er * 128 + dl * 2)),
                          bf2u(__float22bfloat162_rn(make_float2(vn.x, vn.y))),
                          bf2u(__float22bfloat162_rn(make_float2(vn.z, vn.w))));
                    float4* ox = (float4*)(out + grow + d);
                    if (step == 0) {
                        float4 t;
                        t.x = K_C1f * v4.x + K_C2f * vn.x; t.y = K_C1f * v4.y + K_C2f * vn.y;
                        t.z = K_C1f * v4.z + K_C2f * vn.z; t.w = K_C1f * v4.w + K_C2f * vn.w;
                        *ox = t;
                    } else if (step == 1) {
                        float4 t = *ox;
                        t.x += K_C2f * vn.x; t.y += K_C2f * vn.y;
                        t.z += K_C2f * vn.z; t.w += K_C2f * vn.w;
                        *ox = t;
                    } else {
                        float4 t = *ox;
                        float4 x4 = *(const float4*)(x + grow + d);
                        t.x = x4.x + K_DT * (t.x + K_C1f * vn.x);
                        t.y = x4.y + K_DT * (t.y + K_C1f * vn.y);
                        t.z = x4.z + K_DT * (t.z + K_C1f * vn.z);
                        t.w = x4.w + K_DT * (t.w + K_C1f * vn.w);
                        *ox = t;
                        *(float4*)(out + (size_t)BB * DD + grow + d) = vn;
                    }
                }
            }
        }
        __syncthreads();    // SV fully updated before next step's GEMM1 reads
    }
}

extern "C" void kernel_launch(void* const* d_in, const int* in_sizes, int n_in,
                              void* d_out, int out_size)
{
    const float* x     = (const float*)d_in[0];
    const float* v     = (const float*)d_in[1];
    const float* force = (const float*)d_in[2];
    const float* U     = (const float*)d_in[3];
    const float* W     = (const float*)d_in[4];
    float* out = (float*)d_out;

    const int smem_bytes = 229952;
    cudaFuncSetAttribute(yoshida_mma6_kernel, cudaFuncAttributeMaxDynamicSharedMemorySize, smem_bytes);

    prep_uw_kernel<<<1024, 256>>>(U, W);
    yoshida_mma6_kernel<<<NCTA, NTHR, smem_bytes>>>(x, v, force, out);
}